// round 13
// baseline (speedup 1.0000x reference)
#include <cuda_runtime.h>
#include <cuda_fp16.h>
#include <cuda_bf16.h>

#define DIM 256
#define OUT 64
#define ALPHA 0.2f
#define N_MAX 50048
#define E_MAX 1600000
#define SCAN_B 1024
#define MAX_SCAN_BLOCKS ((N_MAX + SCAN_B - 1) / SCAN_B)
#define WT_STRIDE 264   // padded half-stride for Wt rows (conflict-free LDS)

// Scratch (device globals — no allocation allowed)
__device__ __half g_h[N_MAX * OUT];   // h = x @ W (fp16; consumed only by agg)
__device__ float  g_s1[N_MAX];
__device__ float  g_s2[N_MAX];
__device__ int    g_deg[N_MAX];       // histogram (kept as CSR lengths)
__device__ int    g_off[N_MAX];       // block-local exclusive offsets
__device__ int    g_blksum[MAX_SCAN_BLOCKS];
__device__ int    g_rank[E_MAX];      // edge rank within its src (from hist)
__device__ int    g_csr[E_MAX];       // dst indices grouped by src

// bit-cast half2 -> u32 (register alias; no SASS cost)
__device__ __forceinline__ unsigned h2_as_u32(__half2 h) {
    return *reinterpret_cast<unsigned*>(&h);
}

// ---------------------------------------------------------------------------
// Zero degree counters
// ---------------------------------------------------------------------------
__global__ void zero_kernel(int n) {
    int i = blockIdx.x * blockDim.x + threadIdx.x;
    if (i < n) g_deg[i] = 0;
}

// ---------------------------------------------------------------------------
// Histogram: degree per src node; atomic old value = rank of edge within src.
// ---------------------------------------------------------------------------
__global__ void hist_kernel(const int* __restrict__ ei, int e) {
    int i = blockIdx.x * blockDim.x + threadIdx.x;
    if (i < e) g_rank[i] = atomicAdd(&g_deg[ei[i]], 1);
}

// ---------------------------------------------------------------------------
// Scan stage 1: block-local exclusive scan (shuffle-based), 49 blocks
// ---------------------------------------------------------------------------
__global__ void scan1_kernel(int n) {
    int t = threadIdx.x, lane = t & 31, wid = t >> 5;
    int i = blockIdx.x * SCAN_B + t;
    int v = (i < n) ? g_deg[i] : 0;
    int xv = v;
#pragma unroll
    for (int off = 1; off < 32; off <<= 1) {
        int y = __shfl_up_sync(0xFFFFFFFFu, xv, off);
        if (lane >= off) xv += y;
    }
    __shared__ int wsum[32];
    if (lane == 31) wsum[wid] = xv;
    __syncthreads();
    if (wid == 0) {
        int s = wsum[lane];
#pragma unroll
        for (int off = 1; off < 32; off <<= 1) {
            int y = __shfl_up_sync(0xFFFFFFFFu, s, off);
            if (lane >= off) s += y;
        }
        wsum[lane] = s;
    }
    __syncthreads();
    int incl = xv + (wid ? wsum[wid - 1] : 0);
    if (i < n) g_off[i] = incl - v;
    if (t == SCAN_B - 1) g_blksum[blockIdx.x] = incl;
}

// ---------------------------------------------------------------------------
// Scan stage 2: exclusive scan of block sums (single small block)
// ---------------------------------------------------------------------------
__global__ void scan2_kernel(int nb) {
    __shared__ int sh[64];
    int t = threadIdx.x;
    int v = (t < nb) ? g_blksum[t] : 0;
    sh[t] = v;
    __syncthreads();
#pragma unroll
    for (int off = 1; off < 64; off <<= 1) {
        int add = (t >= off) ? sh[t - off] : 0;
        __syncthreads();
        sh[t] += add;
        __syncthreads();
    }
    if (t < nb) g_blksum[t] = sh[t] - v;  // exclusive
}

// ---------------------------------------------------------------------------
// Scatter (atomic-free): pos = off[src] + blksum[src>>10] + rank[i]
// ---------------------------------------------------------------------------
__global__ void scatter_kernel(const int* __restrict__ ei, int e) {
    int i = blockIdx.x * blockDim.x + threadIdx.x;
    if (i >= e) return;
    int src = ei[i];
    int dst = ei[e + i];
    g_csr[g_off[src] + g_blksum[src >> 10] + g_rank[i]] = dst;
}

// ---------------------------------------------------------------------------
// h = x @ W via tensor cores (mma.sync m16n8k16, fp16 in / fp32 accumulate).
// ---------------------------------------------------------------------------
__global__ void __launch_bounds__(256)
gemm_kernel(const float* __restrict__ x,
            const float* __restrict__ W,
            const float* __restrict__ a,
            int n) {
    __shared__ __half sWt[OUT * WT_STRIDE];   // 64 x 264 halves = 33 KB

    // Prologue: convert W [256,64] fp32 -> Wt [64,264] fp16 (transposed)
    for (int j = 0; j < 64; j++) {
        int idx = threadIdx.x + j * 256;      // 0..16383
        int k   = idx >> 6;                   // 0..255
        int nn  = idx & 63;                   // 0..63
        sWt[nn * WT_STRIDE + k] = __float2half(W[k * OUT + nn]);
    }
    __syncthreads();

    int warp = threadIdx.x >> 5;
    int lane = threadIdx.x & 31;
    int grp  = lane >> 2;                     // 0..7
    int tig  = lane & 3;                      // 0..3

    int rowBase = blockIdx.x * 128 + warp * 16;
    if (rowBase >= n) return;
    int rLo = rowBase + grp;
    int rHi = rowBase + grp + 8;
    int rLoC = min(rLo, n - 1);               // clamped for loads
    int rHiC = min(rHi, n - 1);

    const float2* x2 = reinterpret_cast<const float2*>(x);
    const float2* xLo = x2 + (size_t)rLoC * (DIM / 2);
    const float2* xHi = x2 + (size_t)rHiC * (DIM / 2);

    float acc[8][4];
#pragma unroll
    for (int t = 0; t < 8; t++)
#pragma unroll
        for (int c = 0; c < 4; c++) acc[t][c] = 0.f;

#pragma unroll 4
    for (int kc = 0; kc < 16; kc++) {
        int k0 = kc * 16;
        int kh = (k0 >> 1) + tig;             // float2 index of k0 + tig*2

        float2 f0 = xLo[kh];
        float2 f1 = xHi[kh];
        float2 f2 = xLo[kh + 4];
        float2 f3 = xHi[kh + 4];
        unsigned a0 = h2_as_u32(__floats2half2_rn(f0.x, f0.y));
        unsigned a1 = h2_as_u32(__floats2half2_rn(f1.x, f1.y));
        unsigned a2 = h2_as_u32(__floats2half2_rn(f2.x, f2.y));
        unsigned a3 = h2_as_u32(__floats2half2_rn(f3.x, f3.y));

#pragma unroll
        for (int t = 0; t < 8; t++) {
            int nIdx = t * 8 + grp;
            const unsigned* wrow = reinterpret_cast<const unsigned*>(
                sWt + nIdx * WT_STRIDE + k0);
            unsigned b0 = wrow[tig];
            unsigned b1 = wrow[4 + tig];
            asm volatile(
                "mma.sync.aligned.m16n8k16.row.col.f32.f16.f16.f32 "
                "{%0,%1,%2,%3}, {%4,%5,%6,%7}, {%8,%9}, {%0,%1,%2,%3};"
                : "+f"(acc[t][0]), "+f"(acc[t][1]),
                  "+f"(acc[t][2]), "+f"(acc[t][3])
                : "r"(a0), "r"(a1), "r"(a2), "r"(a3), "r"(b0), "r"(b1));
        }
    }

    // Epilogue: store h (fp16) + fused scores
    float p1Lo = 0.f, p2Lo = 0.f, p1Hi = 0.f, p2Hi = 0.f;
#pragma unroll
    for (int t = 0; t < 8; t++) {
        int n0 = t * 8 + tig * 2;
        if (rLo < n)
            *reinterpret_cast<__half2*>(g_h + (size_t)rLo * OUT + n0) =
                __floats2half2_rn(acc[t][0], acc[t][1]);
        if (rHi < n)
            *reinterpret_cast<__half2*>(g_h + (size_t)rHi * OUT + n0) =
                __floats2half2_rn(acc[t][2], acc[t][3]);
        float2 a1v = *reinterpret_cast<const float2*>(a + n0);
        float2 a2v = *reinterpret_cast<const float2*>(a + OUT + n0);
        p1Lo += acc[t][0] * a1v.x + acc[t][1] * a1v.y;
        p2Lo += acc[t][0] * a2v.x + acc[t][1] * a2v.y;
        p1Hi += acc[t][2] * a1v.x + acc[t][3] * a1v.y;
        p2Hi += acc[t][2] * a2v.x + acc[t][3] * a2v.y;
    }
#pragma unroll
    for (int off = 2; off > 0; off >>= 1) {
        p1Lo += __shfl_down_sync(0xFFFFFFFFu, p1Lo, off);
        p2Lo += __shfl_down_sync(0xFFFFFFFFu, p2Lo, off);
        p1Hi += __shfl_down_sync(0xFFFFFFFFu, p1Hi, off);
        p2Hi += __shfl_down_sync(0xFFFFFFFFu, p2Hi, off);
    }
    if (tig == 0) {
        if (rLo < n) { g_s1[rLo] = p1Lo; g_s2[rLo] = p2Lo; }
        if (rHi < n) { g_s1[rHi] = p1Hi; g_s2[rHi] = p2Hi; }
    }
}

// ---------------------------------------------------------------------------
// Aggregate: warp per node. Tail-free padded inner loop (invalid lanes carry
// w=0, dst=0 -> harmless L1-hot row-0 load), full unroll, 2 accumulator
// pairs to halve the FFMA dependence chain and maximize gather MLP.
// ---------------------------------------------------------------------------
__global__ void agg_kernel(float* __restrict__ out, int n) {
    int warp = (blockIdx.x * blockDim.x + threadIdx.x) >> 5;
    int lane = threadIdx.x & 31;
    if (warp >= n) return;

    int start = g_off[warp] + g_blksum[warp >> 10];
    int len   = g_deg[warp];
    float s1n = g_s1[warp];

    float accX0 = 0.f, accY0 = 0.f, accX1 = 0.f, accY1 = 0.f, wsum = 0.f;

    for (int base = 0; base < len; base += 32) {
        int k = base + lane;
        int dstl = 0;
        float wl = 0.f;
        if (k < len) {
            dstl = g_csr[start + k];
            float lg = s1n + g_s2[dstl];
            float lr = lg > 0.f ? lg : ALPHA * lg;
            wl = __expf(-lr);
        }
        wsum += wl;
#pragma unroll
        for (int j = 0; j < 32; j += 2) {
            int   d0 = __shfl_sync(0xFFFFFFFFu, dstl, j);
            float w0 = __shfl_sync(0xFFFFFFFFu, wl, j);
            int   d1 = __shfl_sync(0xFFFFFFFFu, dstl, j + 1);
            float w1 = __shfl_sync(0xFFFFFFFFu, wl, j + 1);
            float2 f0 = __half22float2(*reinterpret_cast<const __half2*>(
                g_h + (size_t)d0 * OUT + lane * 2));
            float2 f1 = __half22float2(*reinterpret_cast<const __half2*>(
                g_h + (size_t)d1 * OUT + lane * 2));
            accX0 += w0 * f0.x;
            accY0 += w0 * f0.y;
            accX1 += w1 * f1.x;
            accY1 += w1 * f1.y;
        }
    }

    float acc0 = accX0 + accX1;
    float acc1 = accY0 + accY1;

#pragma unroll
    for (int off = 16; off > 0; off >>= 1)
        wsum += __shfl_xor_sync(0xFFFFFFFFu, wsum, off);

    float inv = 1.0f / wsum;
    float v0 = acc0 * inv;
    float v1 = acc1 * inv;
    out[(size_t)warp * OUT + lane * 2]     = v0 > 0.f ? v0 : expm1f(v0);
    out[(size_t)warp * OUT + lane * 2 + 1] = v1 > 0.f ? v1 : expm1f(v1);
}

extern "C" void kernel_launch(void* const* d_in, const int* in_sizes, int n_in,
                              void* d_out, int out_size) {
    const float* x  = (const float*)d_in[0];
    const int*   ei = (const int*)d_in[1];
    const float* W  = (const float*)d_in[2];
    const float* a  = (const float*)d_in[3];
    float* out = (float*)d_out;

    int n = in_sizes[0] / DIM;   // 50000
    int e = in_sizes[1] / 2;     // 1600000
    int nb = (n + SCAN_B - 1) / SCAN_B;

    // One-time creation of side stream + events (no device memory involved).
    static cudaStream_t s2 = nullptr;
    static cudaEvent_t ev_fork = nullptr, ev_join = nullptr;
    if (s2 == nullptr) {
        cudaStreamCreateWithFlags(&s2, cudaStreamNonBlocking);
        cudaEventCreateWithFlags(&ev_fork, cudaEventDisableTiming);
        cudaEventCreateWithFlags(&ev_join, cudaEventDisableTiming);
    }

    // Fork: gemm on side stream, CSR build on main stream — independent.
    cudaEventRecord(ev_fork, 0);
    cudaStreamWaitEvent(s2, ev_fork, 0);

    int gemm_blocks = (n + 127) / 128;   // 16 rows/warp x 8 warps
    gemm_kernel<<<gemm_blocks, 256, 0, s2>>>(x, W, a, n);
    cudaEventRecord(ev_join, s2);

    // CSR build chain on main stream — fully overlapped with gemm.
    zero_kernel<<<(n + 255) / 256, 256>>>(n);
    hist_kernel<<<(e + 255) / 256, 256>>>(ei, e);
    scan1_kernel<<<nb, SCAN_B>>>(n);
    scan2_kernel<<<1, 64>>>(nb);
    scatter_kernel<<<(e + 255) / 256, 256>>>(ei, e);

    // Join: agg needs both chains.
    cudaStreamWaitEvent(0, ev_join, 0);
    agg_kernel<<<((long long)n * 32 + 255) / 256, 256>>>(out, n);
}

// round 14
// speedup vs baseline: 1.0373x; 1.0373x over previous
#include <cuda_runtime.h>
#include <cuda_fp16.h>
#include <cuda_bf16.h>

#define DIM 256
#define OUT 64
#define ALPHA 0.2f
#define N_MAX 50048
#define E_MAX 1600000
#define SCAN_B 1024
#define MAX_SCAN_BLOCKS ((N_MAX + SCAN_B - 1) / SCAN_B)
#define WT_STRIDE 264   // padded half-stride for Wt rows (conflict-free LDS)

// Scratch (device globals — no allocation allowed)
__device__ __half g_h[N_MAX * OUT];   // h = x @ W (fp16; consumed only by agg)
__device__ float  g_s1[N_MAX];
__device__ float  g_s2[N_MAX];
__device__ int    g_deg[N_MAX];       // histogram (kept as CSR lengths)
__device__ int    g_off[N_MAX];       // block-local exclusive offsets
__device__ int    g_blksum[MAX_SCAN_BLOCKS];
__device__ int    g_rank[E_MAX];      // edge rank within its src (from hist)
__device__ int    g_csr[E_MAX];       // dst indices grouped by src

// bit-cast half2 -> u32 (register alias; no SASS cost)
__device__ __forceinline__ unsigned h2_as_u32(__half2 h) {
    return *reinterpret_cast<unsigned*>(&h);
}

// ---------------------------------------------------------------------------
// Zero degree counters
// ---------------------------------------------------------------------------
__global__ void zero_kernel(int n) {
    int i = blockIdx.x * blockDim.x + threadIdx.x;
    if (i < n) g_deg[i] = 0;
}

// ---------------------------------------------------------------------------
// Histogram: degree per src node; atomic old value = rank of edge within src.
// ---------------------------------------------------------------------------
__global__ void hist_kernel(const int* __restrict__ ei, int e) {
    int i = blockIdx.x * blockDim.x + threadIdx.x;
    if (i < e) g_rank[i] = atomicAdd(&g_deg[ei[i]], 1);
}

// ---------------------------------------------------------------------------
// Scan stage 1: block-local exclusive scan (shuffle-based), 49 blocks
// ---------------------------------------------------------------------------
__global__ void scan1_kernel(int n) {
    int t = threadIdx.x, lane = t & 31, wid = t >> 5;
    int i = blockIdx.x * SCAN_B + t;
    int v = (i < n) ? g_deg[i] : 0;
    int xv = v;
#pragma unroll
    for (int off = 1; off < 32; off <<= 1) {
        int y = __shfl_up_sync(0xFFFFFFFFu, xv, off);
        if (lane >= off) xv += y;
    }
    __shared__ int wsum[32];
    if (lane == 31) wsum[wid] = xv;
    __syncthreads();
    if (wid == 0) {
        int s = wsum[lane];
#pragma unroll
        for (int off = 1; off < 32; off <<= 1) {
            int y = __shfl_up_sync(0xFFFFFFFFu, s, off);
            if (lane >= off) s += y;
        }
        wsum[lane] = s;
    }
    __syncthreads();
    int incl = xv + (wid ? wsum[wid - 1] : 0);
    if (i < n) g_off[i] = incl - v;
    if (t == SCAN_B - 1) g_blksum[blockIdx.x] = incl;
}

// ---------------------------------------------------------------------------
// Scan stage 2: exclusive scan of block sums (single small block)
// ---------------------------------------------------------------------------
__global__ void scan2_kernel(int nb) {
    __shared__ int sh[64];
    int t = threadIdx.x;
    int v = (t < nb) ? g_blksum[t] : 0;
    sh[t] = v;
    __syncthreads();
#pragma unroll
    for (int off = 1; off < 64; off <<= 1) {
        int add = (t >= off) ? sh[t - off] : 0;
        __syncthreads();
        sh[t] += add;
        __syncthreads();
    }
    if (t < nb) g_blksum[t] = sh[t] - v;  // exclusive
}

// ---------------------------------------------------------------------------
// Scatter (atomic-free, 4 edges/thread via int4):
//   pos = off[src] + blksum[src>>10] + rank[i]
// ---------------------------------------------------------------------------
__global__ void scatter_kernel(const int* __restrict__ ei, int e) {
    int i = (blockIdx.x * blockDim.x + threadIdx.x) * 4;
    if (i + 3 < e) {
        int4 s  = *reinterpret_cast<const int4*>(ei + i);
        int4 d  = *reinterpret_cast<const int4*>(ei + e + i);
        int4 rk = *reinterpret_cast<const int4*>(g_rank + i);
        g_csr[g_off[s.x] + g_blksum[s.x >> 10] + rk.x] = d.x;
        g_csr[g_off[s.y] + g_blksum[s.y >> 10] + rk.y] = d.y;
        g_csr[g_off[s.z] + g_blksum[s.z >> 10] + rk.z] = d.z;
        g_csr[g_off[s.w] + g_blksum[s.w >> 10] + rk.w] = d.w;
    } else {
        for (; i < e; i++) {
            int src = ei[i];
            g_csr[g_off[src] + g_blksum[src >> 10] + g_rank[i]] = ei[e + i];
        }
    }
}

// ---------------------------------------------------------------------------
// h = x @ W via tensor cores (mma.sync m16n8k16, fp16 in / fp32 accumulate).
// ---------------------------------------------------------------------------
__global__ void __launch_bounds__(256)
gemm_kernel(const float* __restrict__ x,
            const float* __restrict__ W,
            const float* __restrict__ a,
            int n) {
    __shared__ __half sWt[OUT * WT_STRIDE];   // 64 x 264 halves = 33 KB

    // Prologue: convert W [256,64] fp32 -> Wt [64,264] fp16 (transposed)
    for (int j = 0; j < 64; j++) {
        int idx = threadIdx.x + j * 256;      // 0..16383
        int k   = idx >> 6;                   // 0..255
        int nn  = idx & 63;                   // 0..63
        sWt[nn * WT_STRIDE + k] = __float2half(W[k * OUT + nn]);
    }
    __syncthreads();

    int warp = threadIdx.x >> 5;
    int lane = threadIdx.x & 31;
    int grp  = lane >> 2;                     // 0..7
    int tig  = lane & 3;                      // 0..3

    int rowBase = blockIdx.x * 128 + warp * 16;
    if (rowBase >= n) return;
    int rLo = rowBase + grp;
    int rHi = rowBase + grp + 8;
    int rLoC = min(rLo, n - 1);               // clamped for loads
    int rHiC = min(rHi, n - 1);

    const float2* x2 = reinterpret_cast<const float2*>(x);
    const float2* xLo = x2 + (size_t)rLoC * (DIM / 2);
    const float2* xHi = x2 + (size_t)rHiC * (DIM / 2);

    float acc[8][4];
#pragma unroll
    for (int t = 0; t < 8; t++)
#pragma unroll
        for (int c = 0; c < 4; c++) acc[t][c] = 0.f;

#pragma unroll 4
    for (int kc = 0; kc < 16; kc++) {
        int k0 = kc * 16;
        int kh = (k0 >> 1) + tig;             // float2 index of k0 + tig*2

        float2 f0 = xLo[kh];
        float2 f1 = xHi[kh];
        float2 f2 = xLo[kh + 4];
        float2 f3 = xHi[kh + 4];
        unsigned a0 = h2_as_u32(__floats2half2_rn(f0.x, f0.y));
        unsigned a1 = h2_as_u32(__floats2half2_rn(f1.x, f1.y));
        unsigned a2 = h2_as_u32(__floats2half2_rn(f2.x, f2.y));
        unsigned a3 = h2_as_u32(__floats2half2_rn(f3.x, f3.y));

#pragma unroll
        for (int t = 0; t < 8; t++) {
            int nIdx = t * 8 + grp;
            const unsigned* wrow = reinterpret_cast<const unsigned*>(
                sWt + nIdx * WT_STRIDE + k0);
            unsigned b0 = wrow[tig];
            unsigned b1 = wrow[4 + tig];
            asm volatile(
                "mma.sync.aligned.m16n8k16.row.col.f32.f16.f16.f32 "
                "{%0,%1,%2,%3}, {%4,%5,%6,%7}, {%8,%9}, {%0,%1,%2,%3};"
                : "+f"(acc[t][0]), "+f"(acc[t][1]),
                  "+f"(acc[t][2]), "+f"(acc[t][3])
                : "r"(a0), "r"(a1), "r"(a2), "r"(a3), "r"(b0), "r"(b1));
        }
    }

    // Epilogue: store h (fp16) + fused scores
    float p1Lo = 0.f, p2Lo = 0.f, p1Hi = 0.f, p2Hi = 0.f;
#pragma unroll
    for (int t = 0; t < 8; t++) {
        int n0 = t * 8 + tig * 2;
        if (rLo < n)
            *reinterpret_cast<__half2*>(g_h + (size_t)rLo * OUT + n0) =
                __floats2half2_rn(acc[t][0], acc[t][1]);
        if (rHi < n)
            *reinterpret_cast<__half2*>(g_h + (size_t)rHi * OUT + n0) =
                __floats2half2_rn(acc[t][2], acc[t][3]);
        float2 a1v = *reinterpret_cast<const float2*>(a + n0);
        float2 a2v = *reinterpret_cast<const float2*>(a + OUT + n0);
        p1Lo += acc[t][0] * a1v.x + acc[t][1] * a1v.y;
        p2Lo += acc[t][0] * a2v.x + acc[t][1] * a2v.y;
        p1Hi += acc[t][2] * a1v.x + acc[t][3] * a1v.y;
        p2Hi += acc[t][2] * a2v.x + acc[t][3] * a2v.y;
    }
#pragma unroll
    for (int off = 2; off > 0; off >>= 1) {
        p1Lo += __shfl_down_sync(0xFFFFFFFFu, p1Lo, off);
        p2Lo += __shfl_down_sync(0xFFFFFFFFu, p2Lo, off);
        p1Hi += __shfl_down_sync(0xFFFFFFFFu, p1Hi, off);
        p2Hi += __shfl_down_sync(0xFFFFFFFFu, p2Hi, off);
    }
    if (tig == 0) {
        if (rLo < n) { g_s1[rLo] = p1Lo; g_s2[rLo] = p2Lo; }
        if (rHi < n) { g_s1[rHi] = p1Hi; g_s2[rHi] = p2Hi; }
    }
}

// ---------------------------------------------------------------------------
// Aggregate: warp per node. Guarded tail (no padding traffic); full batches
// use dual accumulator pairs for shorter FFMA chains + higher gather MLP.
// ---------------------------------------------------------------------------
__global__ void agg_kernel(float* __restrict__ out, int n) {
    int warp = (blockIdx.x * blockDim.x + threadIdx.x) >> 5;
    int lane = threadIdx.x & 31;
    if (warp >= n) return;

    int start = g_off[warp] + g_blksum[warp >> 10];
    int len   = g_deg[warp];
    float s1n = g_s1[warp];

    float accX0 = 0.f, accY0 = 0.f, accX1 = 0.f, accY1 = 0.f, wsum = 0.f;

    for (int base = 0; base < len; base += 32) {
        int k = base + lane;
        int dstl = 0;
        float wl = 0.f;
        if (k < len) {
            dstl = g_csr[start + k];
            float lg = s1n + g_s2[dstl];
            float lr = lg > 0.f ? lg : ALPHA * lg;
            wl = __expf(-lr);
        }
        wsum += wl;
        int m = len - base;
        if (m >= 32) {
#pragma unroll
            for (int j = 0; j < 32; j += 2) {
                int   d0 = __shfl_sync(0xFFFFFFFFu, dstl, j);
                float w0 = __shfl_sync(0xFFFFFFFFu, wl, j);
                int   d1 = __shfl_sync(0xFFFFFFFFu, dstl, j + 1);
                float w1 = __shfl_sync(0xFFFFFFFFu, wl, j + 1);
                float2 f0 = __half22float2(*reinterpret_cast<const __half2*>(
                    g_h + (size_t)d0 * OUT + lane * 2));
                float2 f1 = __half22float2(*reinterpret_cast<const __half2*>(
                    g_h + (size_t)d1 * OUT + lane * 2));
                accX0 += w0 * f0.x;
                accY0 += w0 * f0.y;
                accX1 += w1 * f1.x;
                accY1 += w1 * f1.y;
            }
        } else {
            for (int j = 0; j < m; j++) {
                int   d = __shfl_sync(0xFFFFFFFFu, dstl, j);
                float w = __shfl_sync(0xFFFFFFFFu, wl, j);
                float2 f = __half22float2(*reinterpret_cast<const __half2*>(
                    g_h + (size_t)d * OUT + lane * 2));
                accX0 += w * f.x;
                accY0 += w * f.y;
            }
        }
    }

    float acc0 = accX0 + accX1;
    float acc1 = accY0 + accY1;

#pragma unroll
    for (int off = 16; off > 0; off >>= 1)
        wsum += __shfl_xor_sync(0xFFFFFFFFu, wsum, off);

    float inv = 1.0f / wsum;
    float v0 = acc0 * inv;
    float v1 = acc1 * inv;
    out[(size_t)warp * OUT + lane * 2]     = v0 > 0.f ? v0 : expm1f(v0);
    out[(size_t)warp * OUT + lane * 2 + 1] = v1 > 0.f ? v1 : expm1f(v1);
}

extern "C" void kernel_launch(void* const* d_in, const int* in_sizes, int n_in,
                              void* d_out, int out_size) {
    const float* x  = (const float*)d_in[0];
    const int*   ei = (const int*)d_in[1];
    const float* W  = (const float*)d_in[2];
    const float* a  = (const float*)d_in[3];
    float* out = (float*)d_out;

    int n = in_sizes[0] / DIM;   // 50000
    int e = in_sizes[1] / 2;     // 1600000
    int nb = (n + SCAN_B - 1) / SCAN_B;

    // One-time creation of side stream + events (no device memory involved).
    static cudaStream_t s2 = nullptr;
    static cudaEvent_t ev_fork = nullptr, ev_join = nullptr;
    if (s2 == nullptr) {
        cudaStreamCreateWithFlags(&s2, cudaStreamNonBlocking);
        cudaEventCreateWithFlags(&ev_fork, cudaEventDisableTiming);
        cudaEventCreateWithFlags(&ev_join, cudaEventDisableTiming);
    }

    // Fork: gemm on side stream, CSR build on main stream — independent.
    cudaEventRecord(ev_fork, 0);
    cudaStreamWaitEvent(s2, ev_fork, 0);

    int gemm_blocks = (n + 127) / 128;   // 16 rows/warp x 8 warps
    gemm_kernel<<<gemm_blocks, 256, 0, s2>>>(x, W, a, n);
    cudaEventRecord(ev_join, s2);

    // CSR build chain on main stream — fully overlapped with gemm.
    zero_kernel<<<(n + 255) / 256, 256>>>(n);
    hist_kernel<<<(e + 255) / 256, 256>>>(ei, e);
    scan1_kernel<<<nb, SCAN_B>>>(n);
    scan2_kernel<<<1, 64>>>(nb);
    scatter_kernel<<<((e + 3) / 4 + 255) / 256, 256>>>(ei, e);

    // Join: agg needs both chains.
    cudaStreamWaitEvent(0, ev_join, 0);
    agg_kernel<<<((long long)n * 32 + 255) / 256, 256>>>(out, n);
}